// round 1
// baseline (speedup 1.0000x reference)
#include <cuda_runtime.h>

#define C        128
#define NB       16
#define GROUPS   32
#define CPG      4
#define EPS      1e-5f

// Allocation-free scratch (harness forbids cudaMalloc anywhere).
__device__ float  g_sum[NB][C];
__device__ float  g_sq [NB][C];
__device__ int    g_cnt[NB];
__device__ float2 g_ms [NB][GROUPS];   // (mean, inv_std) per (batch, group)

__global__ void zero_kernel() {
    int i = threadIdx.x;
    float* s = &g_sum[0][0];
    float* q = &g_sq[0][0];
    for (int j = i; j < NB * C; j += blockDim.x) { s[j] = 0.f; q[j] = 0.f; }
    if (i < NB) g_cnt[i] = 0;
}

// Each warp reduces 256 contiguous rows; lane l owns channels [4l, 4l+4).
// batch_id is sorted, so per-warp flushes are rare (<=2 typically).
__global__ void reduce_kernel(const float4* __restrict__ data,
                              const int*    __restrict__ bid,
                              int n) {
    const int RPW  = 256;
    int lane = threadIdx.x & 31;
    int warp = (blockIdx.x * blockDim.x + threadIdx.x) >> 5;
    int r0 = warp * RPW;
    if (r0 >= n) return;
    int r1 = min(n, r0 + RPW);

    float4 s = make_float4(0.f, 0.f, 0.f, 0.f);
    float4 q = make_float4(0.f, 0.f, 0.f, 0.f);
    int cnt = 0;
    int cur = bid[r0];

    for (int r = r0; r < r1; ++r) {
        int b = bid[r];                       // warp-uniform broadcast load
        if (b != cur) {
            int c0 = lane * 4;
            atomicAdd(&g_sum[cur][c0 + 0], s.x);
            atomicAdd(&g_sum[cur][c0 + 1], s.y);
            atomicAdd(&g_sum[cur][c0 + 2], s.z);
            atomicAdd(&g_sum[cur][c0 + 3], s.w);
            atomicAdd(&g_sq [cur][c0 + 0], q.x);
            atomicAdd(&g_sq [cur][c0 + 1], q.y);
            atomicAdd(&g_sq [cur][c0 + 2], q.z);
            atomicAdd(&g_sq [cur][c0 + 3], q.w);
            if (lane == 0) atomicAdd(&g_cnt[cur], cnt);
            s = make_float4(0.f, 0.f, 0.f, 0.f);
            q = make_float4(0.f, 0.f, 0.f, 0.f);
            cnt = 0;
            cur = b;
        }
        float4 v = data[r * 32 + lane];
        s.x += v.x; s.y += v.y; s.z += v.z; s.w += v.w;
        q.x += v.x * v.x; q.y += v.y * v.y; q.z += v.z * v.z; q.w += v.w * v.w;
        cnt++;
    }
    {
        int c0 = lane * 4;
        atomicAdd(&g_sum[cur][c0 + 0], s.x);
        atomicAdd(&g_sum[cur][c0 + 1], s.y);
        atomicAdd(&g_sum[cur][c0 + 2], s.z);
        atomicAdd(&g_sum[cur][c0 + 3], s.w);
        atomicAdd(&g_sq [cur][c0 + 0], q.x);
        atomicAdd(&g_sq [cur][c0 + 1], q.y);
        atomicAdd(&g_sq [cur][c0 + 2], q.z);
        atomicAdd(&g_sq [cur][c0 + 3], q.w);
        if (lane == 0) atomicAdd(&g_cnt[cur], cnt);
    }
}

// One small block: per-(batch, group) mean and inv_std, matching reference math:
//   inv_count = 1/(cnt*CPG + EPS)
//   m_g   = (sum over 4 channels of per-channel sums) * inv_count
//   var_g = (sq_g - 2*m_g*s_g + CPG*cnt*m_g^2) * inv_count
__global__ void stats_kernel() {
    int idx = threadIdx.x;
    if (idx >= NB * GROUPS) return;
    int b = idx >> 5;
    int g = idx & 31;
    float cnt  = (float)g_cnt[b];
    float invc = 1.f / (cnt * (float)CPG + EPS);
    float s = 0.f, sq = 0.f;
#pragma unroll
    for (int k = 0; k < CPG; ++k) {
        s  += g_sum[b][g * 4 + k];
        sq += g_sq [b][g * 4 + k];
    }
    float m   = s * invc;
    float var = (sq - 2.f * m * s + (float)CPG * cnt * m * m) * invc;
    g_ms[b][g] = make_float2(m, rsqrtf(var + EPS));
}

// Lane l covers channels [4l,4l+4) == exactly group l (CPG=4, GROUPS=32).
__global__ void apply_kernel(const float4* __restrict__ data,
                             const float4* __restrict__ w4,
                             const float4* __restrict__ bias4,
                             const int*    __restrict__ bid,
                             float4*       __restrict__ out,
                             int n) {
    int lane   = threadIdx.x & 31;
    int warp   = (blockIdx.x * blockDim.x + threadIdx.x) >> 5;
    int nwarps = (gridDim.x * blockDim.x) >> 5;
    float4 w  = w4[lane];
    float4 bb = bias4[lane];

    for (int r = warp; r < n; r += nwarps) {
        int b = bid[r];                       // warp-uniform
        float2 ms = g_ms[b][lane];            // 4KB table, L1-resident
        float4 v  = data[r * 32 + lane];
        float4 o;
        o.x = (v.x - ms.x) * ms.y * w.x + bb.x;
        o.y = (v.y - ms.x) * ms.y * w.y + bb.y;
        o.z = (v.z - ms.x) * ms.y * w.z + bb.z;
        o.w = (v.w - ms.x) * ms.y * w.w + bb.w;
        out[r * 32 + lane] = o;
    }
}

extern "C" void kernel_launch(void* const* d_in, const int* in_sizes, int n_in,
                              void* d_out, int out_size) {
    const float* data = (const float*)d_in[0];
    const float* w    = (const float*)d_in[1];
    const float* bias = (const float*)d_in[2];
    const int*   bid  = (const int*)d_in[3];
    int n = in_sizes[3];                      // rows (batch_id length)

    zero_kernel<<<1, 256>>>();

    const int RPW = 256;                      // rows per warp in reduce
    int warps  = (n + RPW - 1) / RPW;
    int blocks = (warps + 7) / 8;             // 8 warps / block
    reduce_kernel<<<blocks, 256>>>((const float4*)data, bid, n);

    stats_kernel<<<1, 512>>>();

    apply_kernel<<<2048, 256>>>((const float4*)data, (const float4*)w,
                                (const float4*)bias, bid,
                                (float4*)d_out, n);
}

// round 2
// speedup vs baseline: 1.0807x; 1.0807x over previous
#include <cuda_runtime.h>

#define C        128
#define NB       16
#define GROUPS   32
#define CPG      4
#define EPS      1e-5f

// Allocation-free scratch (harness forbids cudaMalloc anywhere).
__device__ float  g_sum[NB][C];
__device__ float  g_sq [NB][C];
__device__ int    g_seg[NB + 1];       // segment start offsets (sorted batch_id)
__device__ float2 g_ms [NB][GROUPS];   // (mean, inv_std) per (batch, group)

__global__ void zero_kernel() {
    int i = threadIdx.x;
    float* s = &g_sum[0][0];
    float* q = &g_sq[0][0];
    for (int j = i; j < NB * C; j += blockDim.x) { s[j] = 0.f; q[j] = 0.f; }
}

// 17 boundary offsets via binary search: g_seg[b] = first idx with bid[idx] >= b.
__global__ void bounds_kernel(const int* __restrict__ bid, int n) {
    int b = threadIdx.x;
    if (b > NB) return;
    int lo = 0, hi = n;                 // lower_bound(bid, b)
    while (lo < hi) {
        int mid = (lo + hi) >> 1;
        if (bid[mid] < b) lo = mid + 1; else hi = mid;
    }
    g_seg[b] = lo;
}

// Each warp reduces RPW contiguous rows; lane l owns channels [4l, 4l+4).
__global__ void reduce_kernel(const float4* __restrict__ data,
                              const int*    __restrict__ bid,
                              int n) {
    const int RPW  = 256;
    int lane = threadIdx.x & 31;
    int warp = (blockIdx.x * blockDim.x + threadIdx.x) >> 5;
    int r0 = warp * RPW;
    if (r0 >= n) return;
    int r1 = min(n, r0 + RPW);

    int b0 = bid[r0];
    int b1 = bid[r1 - 1];

    if (b0 == b1) {
        // Fast path: whole range in one segment — branch-free, unrolled, high MLP.
        float4 s = make_float4(0.f, 0.f, 0.f, 0.f);
        float4 q = make_float4(0.f, 0.f, 0.f, 0.f);
#pragma unroll 8
        for (int r = r0; r < r1; ++r) {
            float4 v = __ldcs(&data[r * 32 + lane]);
            s.x += v.x; s.y += v.y; s.z += v.z; s.w += v.w;
            q.x += v.x * v.x; q.y += v.y * v.y; q.z += v.z * v.z; q.w += v.w * v.w;
        }
        int c0 = lane * 4;
        atomicAdd(&g_sum[b0][c0 + 0], s.x);
        atomicAdd(&g_sum[b0][c0 + 1], s.y);
        atomicAdd(&g_sum[b0][c0 + 2], s.z);
        atomicAdd(&g_sum[b0][c0 + 3], s.w);
        atomicAdd(&g_sq [b0][c0 + 0], q.x);
        atomicAdd(&g_sq [b0][c0 + 1], q.y);
        atomicAdd(&g_sq [b0][c0 + 2], q.z);
        atomicAdd(&g_sq [b0][c0 + 3], q.w);
    } else {
        // Slow path (<= NB-1 warps total): per-row segment tracking.
        float4 s = make_float4(0.f, 0.f, 0.f, 0.f);
        float4 q = make_float4(0.f, 0.f, 0.f, 0.f);
        int cur = b0;
        for (int r = r0; r < r1; ++r) {
            int b = bid[r];
            if (b != cur) {
                int c0 = lane * 4;
                atomicAdd(&g_sum[cur][c0 + 0], s.x);
                atomicAdd(&g_sum[cur][c0 + 1], s.y);
                atomicAdd(&g_sum[cur][c0 + 2], s.z);
                atomicAdd(&g_sum[cur][c0 + 3], s.w);
                atomicAdd(&g_sq [cur][c0 + 0], q.x);
                atomicAdd(&g_sq [cur][c0 + 1], q.y);
                atomicAdd(&g_sq [cur][c0 + 2], q.z);
                atomicAdd(&g_sq [cur][c0 + 3], q.w);
                s = make_float4(0.f, 0.f, 0.f, 0.f);
                q = make_float4(0.f, 0.f, 0.f, 0.f);
                cur = b;
            }
            float4 v = __ldcs(&data[r * 32 + lane]);
            s.x += v.x; s.y += v.y; s.z += v.z; s.w += v.w;
            q.x += v.x * v.x; q.y += v.y * v.y; q.z += v.z * v.z; q.w += v.w * v.w;
        }
        int c0 = lane * 4;
        atomicAdd(&g_sum[cur][c0 + 0], s.x);
        atomicAdd(&g_sum[cur][c0 + 1], s.y);
        atomicAdd(&g_sum[cur][c0 + 2], s.z);
        atomicAdd(&g_sum[cur][c0 + 3], s.w);
        atomicAdd(&g_sq [cur][c0 + 0], q.x);
        atomicAdd(&g_sq [cur][c0 + 1], q.y);
        atomicAdd(&g_sq [cur][c0 + 2], q.z);
        atomicAdd(&g_sq [cur][c0 + 3], q.w);
    }
}

// Per-(batch, group) mean and inv_std, matching reference math:
//   inv_count = 1/(cnt*CPG + EPS)
//   m_g   = (sum of 4 per-channel sums) * inv_count
//   var_g = (sq_g - 2*m_g*s_g + CPG*cnt*m_g^2) * inv_count
__global__ void stats_kernel() {
    int idx = threadIdx.x;
    if (idx >= NB * GROUPS) return;
    int b = idx >> 5;
    int g = idx & 31;
    float cnt  = (float)(g_seg[b + 1] - g_seg[b]);
    float invc = 1.f / (cnt * (float)CPG + EPS);
    float s = 0.f, sq = 0.f;
#pragma unroll
    for (int k = 0; k < CPG; ++k) {
        s  += g_sum[b][g * 4 + k];
        sq += g_sq [b][g * 4 + k];
    }
    float m   = s * invc;
    float var = (sq - 2.f * m * s + (float)CPG * cnt * m * m) * invc;
    g_ms[b][g] = make_float2(m, rsqrtf(var + EPS));
}

// Lane l covers channels [4l,4l+4) == exactly group l (CPG=4, GROUPS=32).
__global__ void apply_kernel(const float4* __restrict__ data,
                             const float4* __restrict__ w4,
                             const float4* __restrict__ bias4,
                             const int*    __restrict__ bid,
                             float4*       __restrict__ out,
                             int n) {
    int lane   = threadIdx.x & 31;
    int warp   = (blockIdx.x * blockDim.x + threadIdx.x) >> 5;
    int nwarps = (gridDim.x * blockDim.x) >> 5;
    float4 w  = w4[lane];
    float4 bb = bias4[lane];

    for (int r = warp; r < n; r += nwarps) {
        int b = bid[r];                       // warp-uniform
        float2 ms = g_ms[b][lane];            // 4KB table, L1/L2-resident
        float4 v  = __ldcs(&data[r * 32 + lane]);
        float4 o;
        o.x = (v.x - ms.x) * ms.y * w.x + bb.x;
        o.y = (v.y - ms.x) * ms.y * w.y + bb.y;
        o.z = (v.z - ms.x) * ms.y * w.z + bb.z;
        o.w = (v.w - ms.x) * ms.y * w.w + bb.w;
        __stcs(&out[r * 32 + lane], o);
    }
}

extern "C" void kernel_launch(void* const* d_in, const int* in_sizes, int n_in,
                              void* d_out, int out_size) {
    const float* data = (const float*)d_in[0];
    const float* w    = (const float*)d_in[1];
    const float* bias = (const float*)d_in[2];
    const int*   bid  = (const int*)d_in[3];
    int n = in_sizes[3];                      // rows (batch_id length)

    zero_kernel<<<1, 256>>>();
    bounds_kernel<<<1, 32>>>(bid, n);

    const int RPW = 256;                      // rows per warp in reduce
    int warps  = (n + RPW - 1) / RPW;
    int blocks = (warps + 7) / 8;             // 8 warps / block
    reduce_kernel<<<blocks, 256>>>((const float4*)data, bid, n);

    stats_kernel<<<1, 512>>>();

    apply_kernel<<<2048, 256>>>((const float4*)data, (const float4*)w,
                                (const float4*)bias, bid,
                                (float4*)d_out, n);
}